// round 9
// baseline (speedup 1.0000x reference)
#include <cuda_runtime.h>
#include <math.h>

// Problem constants
#define TAU   0.07f
#define BB    8
#define CC    128
#define HH    512
#define WW    512
#define HWSZ  (HH*WW)
#define KK    64
#define NNEG  7
#define PP    4096
#define NQ    (BB*KK)          // 512
#define CPAD  68               // pool smem row stride (words)

// Device scratch (allocation-free; zero-initialized at module load,
// reset by the last block each run for graph replay)
__device__ float4 g_q[NQ * 32];          // RAW gathered queries [NQ][C]
__device__ float  g_pmax_val[NQ * 64];   // per (query, pool-block) max dot*invp
__device__ float  g_loss_blk[64];
__device__ volatile int g_qcnt[8];       // gather arrivals per query-block
__device__ volatile int g_gcnt[8];       // GEMM arrivals per query-block
__device__ int    g_ticket3;

__device__ __forceinline__ void ffma2(unsigned long long& d,
                                      unsigned long long a,
                                      unsigned long long b) {
    asm("fma.rn.f32x2 %0, %1, %2, %0;" : "+l"(d) : "l"(a), "l"(b));
}

// ---------------------------------------------------------------------------
// ONE fused kernel. grid = 512 blocks (bid = qblk*64 + pblk), 128 threads.
// All 512 blocks are co-resident (smem 33.6KB -> >=4 blocks/SM of 148),
// so the producer/consumer flag waits below cannot deadlock.
// ---------------------------------------------------------------------------
__global__ void __launch_bounds__(128, 4)
fused_kernel(const float* __restrict__ qf,
             const float* __restrict__ pool,
             const float* __restrict__ negs,
             const int*   __restrict__ qidx,
             float* __restrict__ out) {
    __shared__ float q_s[64 * 64];      // 16 KB
    __shared__ float p_s[64 * CPAD];    // 17.4 KB
    __shared__ float invp_s[64];
    __shared__ float warp_loss[4];

    int t = threadIdx.x, bid = blockIdx.x;
    int qblk = bid >> 6, pblk = bid & 63;
    int qbase = qblk * 64, pbase = pblk * 64;
    int lane = t & 31;

    // ================= Phase A: scattered gather (1 elem/thread) =============
    // e -> (k fastest, c, b): each warp stays within ONE 2MB page of qf.
    {
        int e = bid * 128 + t;
        int k = e & 63;
        int c = (e >> 6) & 127;
        int b = e >> 13;                 // == qblk for every t in this block
        int idx = qidx[b * KK + k];
        float v = qf[(long)(b * CC + c) * HWSZ + idx];
        ((float*)g_q)[(b * KK + k) * CC + c] = v;
    }
    __syncthreads();
    if (t == 0) {
        __threadfence();
        atomicAdd((int*)&g_qcnt[qblk], 1);
        // wait until all 64 blocks of this qblk have gathered their channels
        while (g_qcnt[qblk] < 64) { __nanosleep(32); }
        __threadfence();
    }
    __syncthreads();

    // ================= Phase B: GEMM 64q x 64p, micro 8q x 4p, f32x2 ========
    int tx = t & 15, ty = t >> 4;       // tx -> p cols, ty (0..7) -> q rows
    unsigned long long acc2[8][4];
    #pragma unroll
    for (int i = 0; i < 8; i++)
        #pragma unroll
        for (int j = 0; j < 4; j++) acc2[i][j] = 0ULL;

    float pss = 0.0f;                    // raw pool-row sumsq (row t>>1)

    for (int kc = 0; kc < 2; kc++) {
        if (kc) __syncthreads();
        #pragma unroll
        for (int it = 0; it < 8; it++) {
            int idx = t + it * 128;
            int r = idx >> 4, c4 = idx & 15;
            float4 v = g_q[(qbase + r) * 32 + kc * 16 + c4];
            *(float4*)(q_s + r * 64 + c4 * 4) = v;
            float4 u = ((const float4*)pool)[(pbase + r) * 32 + kc * 16 + c4];
            *(float4*)(p_s + r * CPAD + c4 * 4) = u;   // RAW
        }
        __syncthreads();

        // pool row sumsq: 2 threads per row, 8 float4 each
        {
            int r = t >> 1, h = t & 1;
            float s = 0.0f;
            #pragma unroll
            for (int j = 0; j < 8; j++) {
                float4 u = *(const float4*)(p_s + r * CPAD + (h * 8 + j) * 4);
                s += u.x*u.x + u.y*u.y + u.z*u.z + u.w*u.w;
            }
            pss += s + __shfl_xor_sync(0xFFFFFFFFu, s, 1);
        }

        #pragma unroll
        for (int c4 = 0; c4 < 16; c4++) {
            union F4 { float4 f; unsigned long long u[2]; } qv, pv[4];
            #pragma unroll
            for (int pj = 0; pj < 4; pj++)
                pv[pj].f = *(const float4*)(p_s + (tx + 16 * pj) * CPAD + c4 * 4);
            #pragma unroll
            for (int qi = 0; qi < 8; qi++) {
                qv.f = *(const float4*)(q_s + (ty * 8 + qi) * 64 + c4 * 4);
                #pragma unroll
                for (int pj = 0; pj < 4; pj++) {
                    ffma2(acc2[qi][pj], qv.u[0], pv[pj].u[0]);
                    ffma2(acc2[qi][pj], qv.u[1], pv[pj].u[1]);
                }
            }
        }
    }

    if ((t & 1) == 0) invp_s[t >> 1] = 1.0f / fmaxf(sqrtf(pss), 1e-12f);
    __syncthreads();

    // epilogue: dot * invp, max over 4 p cols, 16-lane max reduce
    float inv[4];
    #pragma unroll
    for (int pj = 0; pj < 4; pj++) inv[pj] = invp_s[tx + 16 * pj];

    float bv[8];
    #pragma unroll
    for (int qi = 0; qi < 8; qi++) {
        float2 d0 = *(float2*)&acc2[qi][0];
        float2 d1 = *(float2*)&acc2[qi][1];
        float2 d2 = *(float2*)&acc2[qi][2];
        float2 d3 = *(float2*)&acc2[qi][3];
        bv[qi] = fmaxf(fmaxf((d0.x + d0.y) * inv[0], (d1.x + d1.y) * inv[1]),
                       fmaxf((d2.x + d2.y) * inv[2], (d3.x + d3.y) * inv[3]));
    }
    #pragma unroll
    for (int o = 8; o > 0; o >>= 1) {
        #pragma unroll
        for (int qi = 0; qi < 8; qi++)
            bv[qi] = fmaxf(bv[qi], __shfl_xor_sync(0xFFFFFFFFu, bv[qi], o));
    }
    if (tx == 0) {
        #pragma unroll
        for (int qi = 0; qi < 8; qi++)
            g_pmax_val[(qbase + ty * 8 + qi) * 64 + pblk] = bv[qi];
    }
    __syncthreads();
    if (t == 0) {
        __threadfence();
        atomicAdd((int*)&g_gcnt[qblk], 1);
    }

    // ================= Phase C: finalize (blocks with pblk < 8) =============
    if (pblk < 8) {
        if (t == 0) {
            while (g_gcnt[qblk] < 64) { __nanosleep(32); }
            __threadfence();
        }
        __syncthreads();

        int w = t >> 5;
        int fid = qblk * 8 + pblk;       // 0..63; handles queries fid*8..+7
        float myloss = 0.0f;
        #pragma unroll
        for (int qq = 0; qq < 2; qq++) {
            int q = fid * 8 + w * 2 + qq;
            int b = q >> 6, k = q & 63;

            float4 qv = g_q[q * 32 + lane];
            float qss = qv.x*qv.x + qv.y*qv.y + qv.z*qv.z + qv.w*qv.w;
            float v1 = fmaxf(g_pmax_val[q * 64 + lane],
                             g_pmax_val[q * 64 + 32 + lane]);
            #pragma unroll
            for (int o = 16; o > 0; o >>= 1) {
                qss += __shfl_xor_sync(0xFFFFFFFFu, qss, o);
                v1 = fmaxf(v1, __shfl_xor_sync(0xFFFFFFFFu, v1, o));
            }
            float invq = 1.0f / fmaxf(sqrtf(qss), 1e-12f);

            float l[1 + NNEG];
            l[0] = v1 * invq / TAU;
            #pragma unroll
            for (int n = 0; n < NNEG; n++) {
                const float4* np = (const float4*)(negs + (((long)(b * KK + k)) * NNEG + n) * CC);
                float4 nv = np[lane];
                float ss = nv.x*nv.x + nv.y*nv.y + nv.z*nv.z + nv.w*nv.w;
                float dt = nv.x*qv.x + nv.y*qv.y + nv.z*qv.z + nv.w*qv.w;
                #pragma unroll
                for (int o = 16; o > 0; o >>= 1) {
                    ss += __shfl_xor_sync(0xFFFFFFFFu, ss, o);
                    dt += __shfl_xor_sync(0xFFFFFFFFu, dt, o);
                }
                l[n + 1] = (dt * invq / fmaxf(sqrtf(ss), 1e-12f)) / TAU;
            }
            if (lane == 0) {
                float m = l[0];
                #pragma unroll
                for (int i = 1; i <= NNEG; i++) m = fmaxf(m, l[i]);
                float sum = 0.0f;
                #pragma unroll
                for (int i = 0; i <= NNEG; i++) sum += expf(l[i] - m);
                myloss += m + logf(sum) - l[0];
            }
        }
        if (lane == 0) warp_loss[w] = myloss;
        __syncthreads();

        if (t == 0) {
            g_loss_blk[fid] = warp_loss[0] + warp_loss[1] + warp_loss[2] + warp_loss[3];
            __threadfence();
            int tk = atomicAdd(&g_ticket3, 1);
            if (tk == 63) {
                __threadfence();
                // deterministic fixed-order mean over 64 partials
                float tot = 0.0f;
                #pragma unroll
                for (int i = 0; i < 64; i++) tot += g_loss_blk[i];
                out[0] = tot / (float)NQ;
                // reset flags for the next graph replay
                #pragma unroll
                for (int i = 0; i < 8; i++) { g_qcnt[i] = 0; g_gcnt[i] = 0; }
                g_ticket3 = 0;
            }
        }
    }
}

extern "C" void kernel_launch(void* const* d_in, const int* in_sizes, int n_in,
                              void* d_out, int out_size) {
    const float* query_feat = (const float*)d_in[0];
    const float* pos_pool   = (const float*)d_in[1];
    const float* neg_protos = (const float*)d_in[2];
    const int*   query_idx  = (const int*)d_in[3];
    float* out = (float*)d_out;

    fused_kernel<<<512, 128>>>(query_feat, pos_pool, neg_protos, query_idx, out);
}

// round 10
// speedup vs baseline: 1.2125x; 1.2125x over previous
#include <cuda_runtime.h>
#include <math.h>

// Problem constants
#define TAU   0.07f
#define BB    8
#define CC    128
#define HH    512
#define WW    512
#define HWSZ  (HH*WW)
#define KK    64
#define NNEG  7
#define PP    4096
#define NQ    (BB*KK)          // 512
#define CPAD  68               // pool smem row stride (words)
#define NPB   64               // pool blocks of 64 rows

// Device scratch (allocation-free)
__device__ float4 g_q[NQ * 32];          // RAW gathered queries [NQ][C]
__device__ float  g_pinv[PP];            // pool inverse norms
__device__ float  g_pmax_val[NQ * NPB];  // per (query,pool-block) max cos*|q|
__device__ float  g_loss[NQ];
__device__ volatile int g_gcnt[8];       // GEMM arrivals per query-block
__device__ int    g_ticket;

__device__ __forceinline__ void ffma2(unsigned long long& d,
                                      unsigned long long a,
                                      unsigned long long b) {
    asm("fma.rn.f32x2 %0, %1, %2, %0;" : "+l"(d) : "l"(a), "l"(b));
}

// ---------------------------------------------------------------------------
// Kernel 1: gather (TLB-friendly: warp = one (b,c) page, lanes = k)
//           + pool inverse norms + flag/ticket reset. 256 blocks x 256 thr.
// ---------------------------------------------------------------------------
__global__ void __launch_bounds__(256)
prep_kernel(const float* __restrict__ qf,
            const float* __restrict__ pool,
            const int*   __restrict__ qidx) {
    int t = threadIdx.x, bid = blockIdx.x;
    int w = t >> 5, lane = t & 31;
    if (bid == 0 && t < 8) g_gcnt[t] = 0;
    if (bid == 0 && t == 8) g_ticket = 0;

    int e = bid * 256 + t;
    int k = e & 63;
    int c = (e >> 6) & 127;
    int b = e >> 13;
    int idx = qidx[b * KK + k];
    float v = qf[(long)(b * CC + c) * HWSZ + idx];

    #pragma unroll
    for (int j = 0; j < 2; j++) {
        int r = bid * 16 + w * 2 + j;
        float4 u = ((const float4*)pool)[r * 32 + lane];
        float ss = u.x*u.x + u.y*u.y + u.z*u.z + u.w*u.w;
        #pragma unroll
        for (int o = 16; o > 0; o >>= 1) ss += __shfl_xor_sync(0xFFFFFFFFu, ss, o);
        if (lane == 0) g_pinv[r] = 1.0f / fmaxf(sqrtf(ss), 1e-12f);
    }

    ((float*)g_q)[(b * KK + k) * CC + c] = v;
}

// ---------------------------------------------------------------------------
// Kernel 2: GEMM + fused finalize. grid = 512 (bid = qblk*64 + pblk), 128 thr.
// GEMM: tile 64q x 64p, micro 8q x 4p, f32x2 (R7 mainloop, proven).
// After arriving on g_gcnt[qblk], blocks with pblk < 16 finalize: warp = one
// query (16 blk x 4 warps = 64 q per qblk), negs loads hoisted (7 concurrent).
// Ticket-elected last of the 128 finalize blocks does deterministic mean.
// ---------------------------------------------------------------------------
__global__ void __launch_bounds__(128, 4)
gemm_fin_kernel(const float* __restrict__ pool,
                const float* __restrict__ negs,
                float* __restrict__ out) {
    __shared__ float q_s[64 * 64];      // 16 KB
    __shared__ float p_s[64 * CPAD];    // 17.4 KB
    __shared__ int   s_last;

    int t = threadIdx.x, bid = blockIdx.x;
    int tx = t & 15, ty = t >> 4;
    int qblk = bid >> 6, pblk = bid & 63;
    int qbase = qblk * 64, pbase = pblk * 64;
    int w = t >> 5, lane = t & 31;

    unsigned long long acc2[8][4];
    #pragma unroll
    for (int i = 0; i < 8; i++)
        #pragma unroll
        for (int j = 0; j < 4; j++) acc2[i][j] = 0ULL;

    for (int kc = 0; kc < 2; kc++) {
        if (kc) __syncthreads();
        #pragma unroll
        for (int it = 0; it < 8; it++) {
            int idx = t + it * 128;
            int r = idx >> 4, c4 = idx & 15;
            float4 v = g_q[(qbase + r) * 32 + kc * 16 + c4];
            *(float4*)(q_s + r * 64 + c4 * 4) = v;
            float4 u = ((const float4*)pool)[(pbase + r) * 32 + kc * 16 + c4];
            float s = g_pinv[pbase + r];
            u.x *= s; u.y *= s; u.z *= s; u.w *= s;
            *(float4*)(p_s + r * CPAD + c4 * 4) = u;
        }
        __syncthreads();

        #pragma unroll
        for (int c4 = 0; c4 < 16; c4++) {
            union F4 { float4 f; unsigned long long u[2]; } qv, pv[4];
            #pragma unroll
            for (int pj = 0; pj < 4; pj++)
                pv[pj].f = *(const float4*)(p_s + (tx + 16 * pj) * CPAD + c4 * 4);
            #pragma unroll
            for (int qi = 0; qi < 8; qi++) {
                qv.f = *(const float4*)(q_s + (ty * 8 + qi) * 64 + c4 * 4);
                #pragma unroll
                for (int pj = 0; pj < 4; pj++) {
                    ffma2(acc2[qi][pj], qv.u[0], pv[pj].u[0]);
                    ffma2(acc2[qi][pj], qv.u[1], pv[pj].u[1]);
                }
            }
        }
    }

    // epilogue: per-thread max over 4 p cols, 16-lane max reduce, store
    float bv[8];
    #pragma unroll
    for (int qi = 0; qi < 8; qi++) {
        float2 d0 = *(float2*)&acc2[qi][0];
        float2 d1 = *(float2*)&acc2[qi][1];
        float2 d2 = *(float2*)&acc2[qi][2];
        float2 d3 = *(float2*)&acc2[qi][3];
        bv[qi] = fmaxf(fmaxf(d0.x + d0.y, d1.x + d1.y),
                       fmaxf(d2.x + d2.y, d3.x + d3.y));
    }
    #pragma unroll
    for (int o = 8; o > 0; o >>= 1) {
        #pragma unroll
        for (int qi = 0; qi < 8; qi++)
            bv[qi] = fmaxf(bv[qi], __shfl_xor_sync(0xFFFFFFFFu, bv[qi], o));
    }
    if (tx == 0) {
        #pragma unroll
        for (int qi = 0; qi < 8; qi++)
            g_pmax_val[(qbase + ty * 8 + qi) * NPB + pblk] = bv[qi];
    }
    __syncthreads();
    if (t == 0) {
        __threadfence();
        atomicAdd((int*)&g_gcnt[qblk], 1);
    }

    if (pblk >= 16) return;   // non-finalize blocks exit, freeing SM slots

    // ---- fused finalize: warp = one query ----
    if (t == 0) {
        while (g_gcnt[qblk] < 64) { __nanosleep(32); }
        __threadfence();
    }
    __syncthreads();

    int q = qbase + pblk * 4 + w;
    int b = q >> 6, k = q & 63;

    // hoist ALL loads: query vec, 2 pmax partials, 7 negative vecs (independent)
    float4 qv = g_q[q * 32 + lane];
    float pm0 = g_pmax_val[q * NPB + lane];
    float pm1 = g_pmax_val[q * NPB + 32 + lane];
    float4 nv[NNEG];
    const float* nbase = negs + ((long)(b * KK + k)) * NNEG * CC;
    #pragma unroll
    for (int n = 0; n < NNEG; n++)
        nv[n] = ((const float4*)(nbase + n * CC))[lane];

    float qss = qv.x*qv.x + qv.y*qv.y + qv.z*qv.z + qv.w*qv.w;
    float v1 = fmaxf(pm0, pm1);
    float ss[NNEG], dt[NNEG];
    #pragma unroll
    for (int n = 0; n < NNEG; n++) {
        ss[n] = nv[n].x*nv[n].x + nv[n].y*nv[n].y + nv[n].z*nv[n].z + nv[n].w*nv[n].w;
        dt[n] = nv[n].x*qv.x + nv[n].y*qv.y + nv[n].z*qv.z + nv[n].w*qv.w;
    }
    // batched reductions (latency-overlapped shuffles)
    #pragma unroll
    for (int o = 16; o > 0; o >>= 1) {
        qss += __shfl_xor_sync(0xFFFFFFFFu, qss, o);
        v1 = fmaxf(v1, __shfl_xor_sync(0xFFFFFFFFu, v1, o));
        #pragma unroll
        for (int n = 0; n < NNEG; n++) {
            ss[n] += __shfl_xor_sync(0xFFFFFFFFu, ss[n], o);
            dt[n] += __shfl_xor_sync(0xFFFFFFFFu, dt[n], o);
        }
    }
    if (lane == 0) {
        float invq = 1.0f / fmaxf(sqrtf(qss), 1e-12f);
        float l0 = v1 * invq / TAU;
        float m = l0;
        float ln[NNEG];
        #pragma unroll
        for (int n = 0; n < NNEG; n++) {
            ln[n] = (dt[n] * invq / fmaxf(sqrtf(ss[n]), 1e-12f)) / TAU;
            m = fmaxf(m, ln[n]);
        }
        float sum = expf(l0 - m);
        #pragma unroll
        for (int n = 0; n < NNEG; n++) sum += expf(ln[n] - m);
        g_loss[q] = m + logf(sum) - l0;
    }
    __syncthreads();

    if (t == 0) {
        __threadfence();
        int tk = atomicAdd(&g_ticket, 1);
        s_last = (tk == 127) ? 1 : 0;
    }
    __syncthreads();

    if (s_last) {
        // deterministic fixed-order tree reduction over 512 losses
        __shared__ float red[128];
        red[t] = g_loss[t] + g_loss[t + 128] + g_loss[t + 256] + g_loss[t + 384];
        __syncthreads();
        #pragma unroll
        for (int s = 64; s >= 1; s >>= 1) {
            if (t < s) red[t] += red[t + s];
            __syncthreads();
        }
        if (t == 0) out[0] = red[0] / (float)NQ;
    }
}

extern "C" void kernel_launch(void* const* d_in, const int* in_sizes, int n_in,
                              void* d_out, int out_size) {
    const float* query_feat = (const float*)d_in[0];
    const float* pos_pool   = (const float*)d_in[1];
    const float* neg_protos = (const float*)d_in[2];
    const int*   query_idx  = (const int*)d_in[3];
    float* out = (float*)d_out;

    prep_kernel<<<256, 256>>>(query_feat, pos_pool, query_idx);
    gemm_fin_kernel<<<512, 128>>>(pos_pool, neg_protos, out);
}